// round 2
// baseline (speedup 1.0000x reference)
#include <cuda_runtime.h>
#include <cstdint>

// ============================================================================
// QuantizedLinear: out[1024,4096] = x @ W^T + bias
//   W[o, b*8+j] = centroids[assignments[b*4096 + o], j]
//
// sm_103 (base target, no 'a' features): tf32 mma.sync GEMM with cp.async
// 3-stage pipeline. Inputs pre-rounded to tf32 (RNA) and stored in a
// fragment-friendly permuted layout so fragment loads are ld.shared.v4.
// ============================================================================

#define M_DIM 1024
#define N_DIM 4096
#define K_DIM 4096
#define BM 128
#define BN 256
#define BK 32
#define STAGES 3
#define NT (K_DIM / BK)                 // 128 k-tiles
#define A_BYTES (BM * BK * 4)           // 16384
#define B_BYTES (BN * BK * 4)           // 32768
#define STAGE_BYTES (A_BYTES + B_BYTES) // 49152
#define SMEM_TOTAL (STAGES * STAGE_BYTES) // 147456

// Scratch (allocation-free rule): permuted tf32 operands.
// Layout: row-major [rows][K], but within every 16-float k-block the 4x4
// transpose permutation k' = (k&3)*4 + (k>>2) is applied (self-inverse).
__device__ __align__(16) float g_Ap[M_DIM * (size_t)K_DIM];
__device__ __align__(16) float g_Bp[N_DIM * (size_t)K_DIM];

// ---------------------------------------------------------------------------
__device__ __forceinline__ float rna_tf32(float v) {
    asm("cvt.rna.tf32.f32 %0, %1;" : "=f"(v) : "f"(v));
    return v;
}

__device__ __forceinline__ uint32_t smem_u32(const void* p) {
    uint32_t a;
    asm("{ .reg .u64 t; cvta.to.shared.u64 t, %1; cvt.u32.u64 %0, t; }"
        : "=r"(a) : "l"(p));
    return a;
}

__device__ __forceinline__ void cp_async16(uint32_t s, const void* g) {
    asm volatile("cp.async.cg.shared.global [%0], [%1], 16;" :: "r"(s), "l"(g));
}
#define CP_COMMIT() asm volatile("cp.async.commit_group;" ::: "memory")
#define CP_WAIT1()  asm volatile("cp.async.wait_group 1;" ::: "memory")

// Smem chunk swizzle: row has 8 chunks of 16B; swizzle chunk index by
// s(r) = ((r&1)<<2) | (r>>1), r = row & 7. Verified: every quarter-warp's
// eight 16B accesses cover all 32 banks -> conflict-free v4 loads.
__device__ __forceinline__ int swz8(int r) { return ((r & 1) << 2) | (r >> 1); }

__device__ __forceinline__ void mma_tf32(float* c, const uint32_t* a, const uint32_t* b) {
    asm volatile(
        "mma.sync.aligned.m16n8k8.row.col.f32.tf32.tf32.f32 "
        "{%0,%1,%2,%3}, {%4,%5,%6,%7}, {%8,%9}, {%0,%1,%2,%3};"
        : "+f"(c[0]), "+f"(c[1]), "+f"(c[2]), "+f"(c[3])
        : "r"(a[0]), "r"(a[1]), "r"(a[2]), "r"(a[3]), "r"(b[0]), "r"(b[1]));
}

// ---------------------------------------------------------------------------
// Kernel 1: x -> g_Ap (tf32 RNA round + per-16 k-block 4x4 transpose).
// Each thread writes one coalesced float4 of the permuted layout, gathering
// 4 stride-4 floats from x (same 64B span, L1-friendly).
// ---------------------------------------------------------------------------
__global__ void __launch_bounds__(256) prep_x_kernel(const float* __restrict__ x) {
    int o4 = blockIdx.x * 256 + threadIdx.x;       // float4 index, 1M total
    int m = o4 >> 10;                               // 1024 float4 per row
    int c0 = (o4 & 1023) * 4;                       // k' position
    int blk = c0 >> 4;                              // 16-block
    int q = (c0 & 15) >> 2;
    const float* src = x + (size_t)m * K_DIM + blk * 16 + q;
    float4 v;
    v.x = rna_tf32(__ldg(src + 0));
    v.y = rna_tf32(__ldg(src + 4));
    v.z = rna_tf32(__ldg(src + 8));
    v.w = rna_tf32(__ldg(src + 12));
    *reinterpret_cast<float4*>(g_Ap + (size_t)o4 * 4) = v;
}

// ---------------------------------------------------------------------------
// Kernel 2: dequantize W -> g_Bp [N][K] permuted, tf32-rounded.
// Block: 64 out-features x 128 K. Stage assignments in smem for reuse.
// ---------------------------------------------------------------------------
__global__ void __launch_bounds__(256) prep_w_kernel(const int* __restrict__ assign,
                                                     const float* __restrict__ cent) {
    __shared__ int s_cid[16 * 64];                  // [b_local][n_local]
    const int n0 = blockIdx.x * 64;
    const int kb0 = blockIdx.y * 128;               // K range start
    const int b0 = kb0 >> 3;                        // 16 in-blocks
    const int tid = threadIdx.x;

#pragma unroll
    for (int i = 0; i < 4; i++) {
        int idx = tid + i * 256;                    // 1024 entries
        int bl = idx >> 6, nl = idx & 63;
        s_cid[bl * 64 + nl] = assign[(size_t)(b0 + bl) * N_DIM + n0 + nl];
    }
    __syncthreads();

#pragma unroll
    for (int i = 0; i < 8; i++) {                   // 2048 float4 outputs
        int l = tid + i * 256;
        int nl = l >> 5;                            // 32 float4 per n-row
        int c0 = (l & 31) * 4;                      // local k' 0..127
        int blk = c0 >> 4;
        int q = (c0 & 15) >> 2;
        float4 v;
#pragma unroll
        for (int j = 0; j < 4; j++) {
            int klocal = blk * 16 + j * 4 + q;      // un-permuted local k
            int bl = klocal >> 3;
            int jj = klocal & 7;
            int cid = s_cid[bl * 64 + nl];
            ((float*)&v)[j] = rna_tf32(__ldg(cent + (size_t)cid * 8 + jj));
        }
        *reinterpret_cast<float4*>(
            g_Bp + (size_t)(n0 + nl) * K_DIM + kb0 + c0) = v;
    }
}

// ---------------------------------------------------------------------------
// Kernel 3: GEMM. grid (N/BN=16, M/BM=8), 256 threads, warp grid 2(m) x 4(n),
// warp tile 64x64, mma.m16n8k8 tf32, 3-stage cp.async pipeline.
// ---------------------------------------------------------------------------
__device__ __forceinline__ void load_tile(uint32_t smem_base, char /*unused*/,
                                          int stage,
                                          const float* __restrict__ Ab,
                                          const float* __restrict__ Bb,
                                          int kt, int tid) {
    uint32_t sA = smem_base + stage * STAGE_BYTES;
    uint32_t sB = sA + A_BYTES;
    const float* Ag = Ab + kt * BK;
    const float* Bg = Bb + kt * BK;
#pragma unroll
    for (int i = 0; i < 4; i++) {                   // A: 1024 16B chunks
        int c = tid + i * 256;
        int row = c >> 3, ck = c & 7;
        uint32_t dst = sA + row * 128 + (uint32_t)((ck ^ swz8(row & 7)) << 4);
        cp_async16(dst, Ag + (size_t)row * K_DIM + ck * 4);
    }
#pragma unroll
    for (int i = 0; i < 8; i++) {                   // B: 2048 16B chunks
        int c = tid + i * 256;
        int row = c >> 3, ck = c & 7;
        uint32_t dst = sB + row * 128 + (uint32_t)((ck ^ swz8(row & 7)) << 4);
        cp_async16(dst, Bg + (size_t)row * K_DIM + ck * 4);
    }
}

__global__ void __launch_bounds__(256, 1)
gemm_kernel(const float* __restrict__ bias, float* __restrict__ out) {
    extern __shared__ char dsm[];
    const uint32_t smem_base = smem_u32(dsm);
    const int tid = threadIdx.x;
    const int lane = tid & 31;
    const int wid = tid >> 5;
    const int gid = lane >> 2;                      // group id 0..7
    const int tig = lane & 3;                       // thread-in-group
    const int sw = swz8(gid);
    const int wm0 = (wid >> 2) * 64;                // warp m offset (0,64)
    const int wn0 = (wid & 3) * 64;                 // warp n offset (0..192)
    const int m0 = blockIdx.y * BM;
    const int n0 = blockIdx.x * BN;

    const float* Ab = g_Ap + (size_t)m0 * K_DIM;
    const float* Bb = g_Bp + (size_t)n0 * K_DIM;

    float acc[4][8][4];
#pragma unroll
    for (int mt = 0; mt < 4; mt++)
#pragma unroll
        for (int nt = 0; nt < 8; nt++)
#pragma unroll
            for (int r = 0; r < 4; r++) acc[mt][nt][r] = 0.0f;

    // Prologue: stages 0,1
    load_tile(smem_base, 0, 0, Ab, Bb, 0, tid);
    CP_COMMIT();
    load_tile(smem_base, 0, 1, Ab, Bb, 1, tid);
    CP_COMMIT();

    for (int kt = 0; kt < NT; kt++) {
        CP_WAIT1();                                 // tile kt resident
        __syncthreads();                            // visible to all; stage kt-1 free

        int ld = kt + 2;
        if (ld < NT) load_tile(smem_base, 0, ld % STAGES, Ab, Bb, ld, tid);
        CP_COMMIT();                                // keep group count uniform

        const int stage = kt % STAGES;
        const char* sa = dsm + stage * STAGE_BYTES;
        const char* sb = sa + A_BYTES;

#pragma unroll
        for (int h = 0; h < 2; h++) {               // two 16-k halves
            const uint32_t coff = (uint32_t)(((4 * h + tig) ^ sw) << 4);
            uint32_t af[8][4];                      // [mt*2 + hilo][4 k-vals]
#pragma unroll
            for (int mt = 0; mt < 4; mt++) {
                int rlo = wm0 + mt * 16 + gid;
                float4 vlo = *reinterpret_cast<const float4*>(sa + rlo * 128 + coff);
                float4 vhi = *reinterpret_cast<const float4*>(sa + (rlo + 8) * 128 + coff);
                af[mt * 2][0] = __float_as_uint(vlo.x);
                af[mt * 2][1] = __float_as_uint(vlo.y);
                af[mt * 2][2] = __float_as_uint(vlo.z);
                af[mt * 2][3] = __float_as_uint(vlo.w);
                af[mt * 2 + 1][0] = __float_as_uint(vhi.x);
                af[mt * 2 + 1][1] = __float_as_uint(vhi.y);
                af[mt * 2 + 1][2] = __float_as_uint(vhi.z);
                af[mt * 2 + 1][3] = __float_as_uint(vhi.w);
            }
            uint32_t bf[8][4];
#pragma unroll
            for (int nt = 0; nt < 8; nt++) {
                int row = wn0 + nt * 8 + gid;
                float4 v = *reinterpret_cast<const float4*>(sb + row * 128 + coff);
                bf[nt][0] = __float_as_uint(v.x);
                bf[nt][1] = __float_as_uint(v.y);
                bf[nt][2] = __float_as_uint(v.z);
                bf[nt][3] = __float_as_uint(v.w);
            }
#pragma unroll
            for (int s = 0; s < 2; s++) {           // k-steps within half
#pragma unroll
                for (int mt = 0; mt < 4; mt++) {
                    uint32_t a[4] = {af[mt * 2][2 * s],     af[mt * 2 + 1][2 * s],
                                     af[mt * 2][2 * s + 1], af[mt * 2 + 1][2 * s + 1]};
#pragma unroll
                    for (int nt = 0; nt < 8; nt++) {
                        uint32_t b[2] = {bf[nt][2 * s], bf[nt][2 * s + 1]};
                        mma_tf32(acc[mt][nt], a, b);
                    }
                }
            }
        }
    }

    // Epilogue: C fragment c0,c1 -> (row gid, cols tig*2, tig*2+1);
    // c2,c3 -> row gid+8.
#pragma unroll
    for (int mt = 0; mt < 4; mt++) {
        int mlo = m0 + wm0 + mt * 16 + gid;
#pragma unroll
        for (int nt = 0; nt < 8; nt++) {
            int n = n0 + wn0 + nt * 8 + tig * 2;
            float bx = __ldg(bias + n);
            float by = __ldg(bias + n + 1);
            float2 v0 = {acc[mt][nt][0] + bx, acc[mt][nt][1] + by};
            float2 v1 = {acc[mt][nt][2] + bx, acc[mt][nt][3] + by};
            *reinterpret_cast<float2*>(out + (size_t)mlo * N_DIM + n) = v0;
            *reinterpret_cast<float2*>(out + (size_t)(mlo + 8) * N_DIM + n) = v1;
        }
    }
}

// ---------------------------------------------------------------------------
extern "C" void kernel_launch(void* const* d_in, const int* in_sizes, int n_in,
                              void* d_out, int out_size) {
    const float* x = nullptr;
    const float* cent = nullptr;
    const float* bias = nullptr;
    const int* assign = nullptr;
    // Inputs by element count: x=4194304, centroids=16384, bias=4096,
    // assignments=2097152, counts=2048 (unused).
    for (int i = 0; i < n_in; i++) {
        switch (in_sizes[i]) {
            case M_DIM * K_DIM:        x = (const float*)d_in[i]; break;
            case 2048 * 8:             cent = (const float*)d_in[i]; break;
            case N_DIM:                bias = (const float*)d_in[i]; break;
            case (K_DIM / 8) * N_DIM:  assign = (const int*)d_in[i]; break;
            default: break;
        }
    }

    static bool attr_done = false;
    if (!attr_done) {
        cudaFuncSetAttribute(gemm_kernel,
                             cudaFuncAttributeMaxDynamicSharedMemorySize, SMEM_TOTAL);
        attr_done = true;
    }

    prep_x_kernel<<<(M_DIM * K_DIM / 4) / 256, 256>>>(x);
    prep_w_kernel<<<dim3(N_DIM / 64, K_DIM / 128), 256>>>(assign, cent);
    gemm_kernel<<<dim3(N_DIM / BN, M_DIM / BM), 256, SMEM_TOTAL>>>(
        bias, (float*)d_out);
}

// round 3
// speedup vs baseline: 1.9384x; 1.9384x over previous
#include <cuda_runtime.h>
#include <cuda_fp16.h>
#include <cstdint>

// ============================================================================
// QuantizedLinear: out[1024,4096] = x @ W^T + bias
//   W[o, b*8+j] = centroids[assignments[b*4096 + o], j]
//
// sm_103 base target (no tcgen05 on this harness): fp16 mma.sync.m16n8k16
// GEMM with f32 accumulation. fp16 has the same 10 mantissa bits as tf32,
// so accuracy matches the tf32 run (~3e-4) at half the instruction count,
// half the smem traffic, and half the global streaming.
// ============================================================================

#define M_DIM 1024
#define N_DIM 4096
#define K_DIM 4096
#define BM 128
#define BN 256
#define BK 64                            // 64 k per tile -> 128B fp16 rows
#define STAGES 4
#define NT (K_DIM / BK)                  // 64 k-tiles
#define A_BYTES (BM * 128)               // 16384
#define B_BYTES (BN * 128)               // 32768
#define STAGE_BYTES (A_BYTES + B_BYTES)  // 49152
#define SMEM_TOTAL (STAGES * STAGE_BYTES) // 196608

// Scratch (allocation-free rule): fp16 operands in fragment-friendly layout.
// Row-major [row][K], but each 16-k block is stored in the permuted order
// {0,1,8,9,2,3,10,11,4,5,12,13,6,7,14,15} so that one 8B read per row gives
// a thread both halves of its mma fragment pair.
__device__ __align__(16) __half g_Ap[(size_t)M_DIM * K_DIM];
__device__ __align__(16) __half g_Bp[(size_t)N_DIM * K_DIM];

// ---------------------------------------------------------------------------
__device__ __forceinline__ uint32_t smem_u32(const void* p) {
    uint32_t a;
    asm("{ .reg .u64 t; cvta.to.shared.u64 t, %1; cvt.u32.u64 %0, t; }"
        : "=r"(a) : "l"(p));
    return a;
}

__device__ __forceinline__ void cp_async16(uint32_t s, const void* g) {
    asm volatile("cp.async.cg.shared.global [%0], [%1], 16;" :: "r"(s), "l"(g));
}
#define CP_COMMIT() asm volatile("cp.async.commit_group;" ::: "memory")
#define CP_WAIT2()  asm volatile("cp.async.wait_group 2;" ::: "memory")

__device__ __forceinline__ void mma_f16(float* c, const uint32_t* a, const uint32_t* b) {
    asm volatile(
        "mma.sync.aligned.m16n8k16.row.col.f32.f16.f16.f32 "
        "{%0,%1,%2,%3}, {%4,%5,%6,%7}, {%8,%9}, {%0,%1,%2,%3};"
        : "+f"(c[0]), "+f"(c[1]), "+f"(c[2]), "+f"(c[3])
        : "r"(a[0]), "r"(a[1]), "r"(a[2]), "r"(a[3]), "r"(b[0]), "r"(b[1]));
}

// ---------------------------------------------------------------------------
// Prep (single kernel, 4096 blocks):
//   blocks [0,2048):   x -> g_Ap  (fp16 rn, permuted 16-k blocks)
//   blocks [2048,4096): dequant W -> g_Bp (fp16 rn, permuted), [N][K] layout
// ---------------------------------------------------------------------------
__global__ void __launch_bounds__(256) prep_kernel(const float* __restrict__ x,
                                                   const int* __restrict__ assign,
                                                   const float* __restrict__ cent) {
    __shared__ int s_cid[16 * 64];
    const int b = blockIdx.x;
    const int tid = threadIdx.x;

    if (b < 2048) {
        // One 16B chunk (8 fp16) per thread. 512 chunks per row.
        int c8 = b * 256 + tid;
        int m = c8 >> 9;
        int ck = c8 & 511;
        int kb = ck >> 1;                 // 16-k block
        int half = ck & 1;
        const float* src = x + (size_t)m * K_DIM + kb * 16 + half * 4;
        // chunk k order (block-relative): {h4+0,h4+1,h4+8,h4+9,h4+2,h4+3,h4+10,h4+11}
        __half2 o[4];
        o[0] = __floats2half2_rn(__ldg(src + 0), __ldg(src + 1));
        o[1] = __floats2half2_rn(__ldg(src + 8), __ldg(src + 9));
        o[2] = __floats2half2_rn(__ldg(src + 2), __ldg(src + 3));
        o[3] = __floats2half2_rn(__ldg(src + 10), __ldg(src + 11));
        *reinterpret_cast<uint4*>(g_Ap + (size_t)c8 * 8) =
            *reinterpret_cast<uint4*>(o);
    } else {
        const int wb = b - 2048;
        const int n0 = (wb & 63) * 64;        // 64 out-features
        const int kb0 = (wb >> 6) * 128;      // 128 K per block
        const int b0 = kb0 >> 3;              // 16 in-blocks
#pragma unroll
        for (int i = 0; i < 4; i++) {
            int idx = tid + i * 256;          // 1024 assignment entries
            int bl = idx >> 6, nl = idx & 63;
            s_cid[bl * 64 + nl] = assign[(size_t)(b0 + bl) * N_DIM + n0 + nl];
        }
        __syncthreads();

        const int koffs[8] = {0, 1, 8, 9, 2, 3, 10, 11};
#pragma unroll
        for (int i = 0; i < 4; i++) {
            int l = tid + i * 256;            // 1024 chunks: 64 rows x 16
            int nl = l >> 4;
            int ck = l & 15;
            int kbase = (ck >> 1) * 16 + (ck & 1) * 4;   // local k base
            float v[8];
#pragma unroll
            for (int j = 0; j < 8; j++) {
                int kl = kbase + koffs[j];
                int cid = s_cid[(kl >> 3) * 64 + nl];
                v[j] = __ldg(cent + (size_t)cid * 8 + (kl & 7));
            }
            __half2 o[4];
            o[0] = __floats2half2_rn(v[0], v[1]);
            o[1] = __floats2half2_rn(v[2], v[3]);
            o[2] = __floats2half2_rn(v[4], v[5]);
            o[3] = __floats2half2_rn(v[6], v[7]);
            *reinterpret_cast<uint4*>(
                g_Bp + (size_t)(n0 + nl) * K_DIM + kb0 + ck * 8) =
                *reinterpret_cast<uint4*>(o);
        }
    }
}

// ---------------------------------------------------------------------------
// GEMM: grid (N/BN=16, M/BM=8), 256 threads, warp grid 2(m) x 4(n),
// warp tile 64x64, mma.m16n8k16 f16/f32, 4-stage cp.async pipeline.
// Smem rows are 128B (64 fp16); 16B-chunk swizzle: c ^= (row&3)*2.
// ---------------------------------------------------------------------------
__device__ __forceinline__ void load_tile(uint32_t smem_base, int stage,
                                          const __half* __restrict__ Ab,
                                          const __half* __restrict__ Bb,
                                          int kt, int tid) {
    uint32_t sA = smem_base + stage * STAGE_BYTES;
    uint32_t sB = sA + A_BYTES;
    const __half* Ag = Ab + kt * BK;
    const __half* Bg = Bb + kt * BK;
#pragma unroll
    for (int i = 0; i < 4; i++) {            // A: 1024 16B chunks
        int c = tid + i * 256;
        int row = c >> 3, ck = c & 7;
        uint32_t dst = sA + row * 128 + (uint32_t)((ck ^ ((row & 3) * 2)) << 4);
        cp_async16(dst, Ag + (size_t)row * K_DIM + ck * 8);
    }
#pragma unroll
    for (int i = 0; i < 8; i++) {            // B: 2048 16B chunks
        int c = tid + i * 256;
        int row = c >> 3, ck = c & 7;
        uint32_t dst = sB + row * 128 + (uint32_t)((ck ^ ((row & 3) * 2)) << 4);
        cp_async16(dst, Bg + (size_t)row * K_DIM + ck * 8);
    }
}

__global__ void __launch_bounds__(256, 1)
gemm_kernel(const float* __restrict__ bias, float* __restrict__ out) {
    extern __shared__ char dsm[];
    const uint32_t smem_base = smem_u32(dsm);
    const int tid = threadIdx.x;
    const int lane = tid & 31;
    const int wid = tid >> 5;
    const int gid = lane >> 2;               // 0..7
    const int tig = lane & 3;                // 0..3
    const int wm0 = (wid >> 2) * 64;
    const int wn0 = (wid & 3) * 64;
    const int m0 = blockIdx.y * BM;
    const int n0 = blockIdx.x * BN;

    const __half* Ab = g_Ap + (size_t)m0 * K_DIM;
    const __half* Bb = g_Bp + (size_t)n0 * K_DIM;

    float acc[4][8][4];
#pragma unroll
    for (int mt = 0; mt < 4; mt++)
#pragma unroll
        for (int nt = 0; nt < 8; nt++)
#pragma unroll
            for (int r = 0; r < 4; r++) acc[mt][nt][r] = 0.0f;

    // Prologue: stages 0..2
#pragma unroll
    for (int t = 0; t < STAGES - 1; t++) {
        load_tile(smem_base, t, Ab, Bb, t, tid);
        CP_COMMIT();
    }

    // Per-thread swizzled sub-offset pieces (row&3 == gid&3 for all frag rows)
    const uint32_t swz_x = (uint32_t)((gid & 3) * 2);
    const uint32_t sub8 = (uint32_t)((tig & 1) << 3);

    for (int kt = 0; kt < NT; kt++) {
        CP_WAIT2();                          // tile kt resident
        __syncthreads();                     // stage kt-1 now free everywhere

        int ld = kt + STAGES - 1;
        if (ld < NT) load_tile(smem_base, ld & (STAGES - 1), Ab, Bb, ld, tid);
        CP_COMMIT();

        const char* sa = dsm + (kt & (STAGES - 1)) * STAGE_BYTES;
        const char* sb = sa + A_BYTES;

#pragma unroll
        for (int kb = 0; kb < 4; kb++) {     // four 16-k blocks
            const uint32_t coff =
                (uint32_t)((((kb * 2 + (tig >> 1)) ^ swz_x) << 4) | sub8);
            uint32_t a[4][4];
#pragma unroll
            for (int mt = 0; mt < 4; mt++) {
                int rlo = wm0 + mt * 16 + gid;
                uint2 lo = *reinterpret_cast<const uint2*>(sa + rlo * 128 + coff);
                uint2 hi = *reinterpret_cast<const uint2*>(sa + (rlo + 8) * 128 + coff);
                a[mt][0] = lo.x; a[mt][2] = lo.y;   // a0,a2 (row gid)
                a[mt][1] = hi.x; a[mt][3] = hi.y;   // a1,a3 (row gid+8)
            }
            uint32_t bb[8][2];
#pragma unroll
            for (int nt = 0; nt < 8; nt++) {
                int r = wn0 + nt * 8 + gid;
                uint2 v = *reinterpret_cast<const uint2*>(sb + r * 128 + coff);
                bb[nt][0] = v.x; bb[nt][1] = v.y;
            }
#pragma unroll
            for (int mt = 0; mt < 4; mt++)
#pragma unroll
                for (int nt = 0; nt < 8; nt++)
                    mma_f16(acc[mt][nt], a[mt], bb[nt]);
        }
    }

    // Epilogue: c0,c1 -> (row gid, cols tig*2,+1); c2,c3 -> row gid+8.
#pragma unroll
    for (int mt = 0; mt < 4; mt++) {
        int mlo = m0 + wm0 + mt * 16 + gid;
#pragma unroll
        for (int nt = 0; nt < 8; nt++) {
            int n = n0 + wn0 + nt * 8 + tig * 2;
            float bx = __ldg(bias + n);
            float by = __ldg(bias + n + 1);
            float2 v0 = {acc[mt][nt][0] + bx, acc[mt][nt][1] + by};
            float2 v1 = {acc[mt][nt][2] + bx, acc[mt][nt][3] + by};
            *reinterpret_cast<float2*>(out + (size_t)mlo * N_DIM + n) = v0;
            *reinterpret_cast<float2*>(out + (size_t)(mlo + 8) * N_DIM + n) = v1;
        }
    }
}

// ---------------------------------------------------------------------------
extern "C" void kernel_launch(void* const* d_in, const int* in_sizes, int n_in,
                              void* d_out, int out_size) {
    const float* x = nullptr;
    const float* cent = nullptr;
    const float* bias = nullptr;
    const int* assign = nullptr;
    // Inputs by element count: x=4194304, centroids=16384, bias=4096,
    // assignments=2097152, counts=2048 (unused).
    for (int i = 0; i < n_in; i++) {
        switch (in_sizes[i]) {
            case M_DIM * K_DIM:        x = (const float*)d_in[i]; break;
            case 2048 * 8:             cent = (const float*)d_in[i]; break;
            case N_DIM:                bias = (const float*)d_in[i]; break;
            case (K_DIM / 8) * N_DIM:  assign = (const int*)d_in[i]; break;
            default: break;
        }
    }

    static bool attr_done = false;
    if (!attr_done) {
        cudaFuncSetAttribute(gemm_kernel,
                             cudaFuncAttributeMaxDynamicSharedMemorySize, SMEM_TOTAL);
        attr_done = true;
    }

    prep_kernel<<<4096, 256>>>(x, assign, cent);
    gemm_kernel<<<dim3(N_DIM / BN, M_DIM / BM), 256, SMEM_TOTAL>>>(
        bias, (float*)d_out);
}

// round 4
// speedup vs baseline: 1.9616x; 1.0119x over previous
#include <cuda_runtime.h>
#include <cuda_fp16.h>
#include <cstdint>

// ============================================================================
// QuantizedLinear: out[1024,4096] = x @ W^T + bias
//   W[o, b*8+j] = centroids[assignments[b*4096 + o], j]
//
// fp16 mma.sync.m16n8k16 (f32 accum) GEMM. R4: 512-thread CTAs (16 warps/SM,
// 4/SMSP) to hide barrier + LDS latency and push the tensor pipe toward its
// ~56us issue floor; prep_w rewritten to vectorized LDG.128 gathers.
// ============================================================================

#define M_DIM 1024
#define N_DIM 4096
#define K_DIM 4096
#define BM 128
#define BN 256
#define BK 64                            // 64 k per tile -> 128B fp16 rows
#define STAGES 4
#define NT (K_DIM / BK)                  // 64 k-tiles
#define A_BYTES (BM * 128)               // 16384
#define B_BYTES (BN * 128)               // 32768
#define STAGE_BYTES (A_BYTES + B_BYTES)  // 49152
#define SMEM_TOTAL (STAGES * STAGE_BYTES) // 196608
#define THREADS 512

// Scratch (allocation-free rule): fp16 operands in fragment-friendly layout.
// Row-major [row][K]; each 16-k block stored in permuted order
// {0,1,8,9,2,3,10,11, 4,5,12,13,6,7,14,15} so one 8B read per row yields a
// thread's mma fragment pair.
__device__ __align__(16) __half g_Ap[(size_t)M_DIM * K_DIM];
__device__ __align__(16) __half g_Bp[(size_t)N_DIM * K_DIM];

// ---------------------------------------------------------------------------
__device__ __forceinline__ uint32_t smem_u32(const void* p) {
    uint32_t a;
    asm("{ .reg .u64 t; cvta.to.shared.u64 t, %1; cvt.u32.u64 %0, t; }"
        : "=r"(a) : "l"(p));
    return a;
}

__device__ __forceinline__ void cp_async16(uint32_t s, const void* g) {
    asm volatile("cp.async.cg.shared.global [%0], [%1], 16;" :: "r"(s), "l"(g));
}
#define CP_COMMIT() asm volatile("cp.async.commit_group;" ::: "memory")
#define CP_WAIT2()  asm volatile("cp.async.wait_group 2;" ::: "memory")

__device__ __forceinline__ void mma_f16(float* c, const uint32_t* a, const uint32_t* b) {
    asm volatile(
        "mma.sync.aligned.m16n8k16.row.col.f32.f16.f16.f32 "
        "{%0,%1,%2,%3}, {%4,%5,%6,%7}, {%8,%9}, {%0,%1,%2,%3};"
        : "+f"(c[0]), "+f"(c[1]), "+f"(c[2]), "+f"(c[3])
        : "r"(a[0]), "r"(a[1]), "r"(a[2]), "r"(a[3]), "r"(b[0]), "r"(b[1]));
}

// ---------------------------------------------------------------------------
// Prep (single kernel, 4096 blocks of 256):
//   blocks [0,2048):   x -> g_Ap  (fp16 rn, permuted 16-k blocks)
//   blocks [2048,4096): dequant W -> g_Bp. Each thread builds ONE 16B output
//   chunk from two LDG.128 centroid-row halves; STG.128 fully coalesced.
// ---------------------------------------------------------------------------
__global__ void __launch_bounds__(256) prep_kernel(const float* __restrict__ x,
                                                   const int* __restrict__ assign,
                                                   const float* __restrict__ cent) {
    __shared__ int s_cid[16 * 64];
    const int b = blockIdx.x;
    const int tid = threadIdx.x;

    if (b < 2048) {
        int c8 = b * 256 + tid;           // 16B chunk index (8 fp16)
        int m = c8 >> 9;                  // 512 chunks per row
        int ck = c8 & 511;
        int kb = ck >> 1;                 // 16-k block
        int half = ck & 1;
        const float* src = x + (size_t)m * K_DIM + kb * 16 + half * 4;
        __half2 o[4];
        o[0] = __floats2half2_rn(__ldg(src + 0), __ldg(src + 1));
        o[1] = __floats2half2_rn(__ldg(src + 8), __ldg(src + 9));
        o[2] = __floats2half2_rn(__ldg(src + 2), __ldg(src + 3));
        o[3] = __floats2half2_rn(__ldg(src + 10), __ldg(src + 11));
        *reinterpret_cast<uint4*>(g_Ap + (size_t)c8 * 8) =
            *reinterpret_cast<uint4*>(o);
    } else {
        const int wb = b - 2048;
        const int n0 = (wb & 63) * 64;        // 64 out-features per block
        const int kb0 = (wb >> 6) * 128;      // 128 K per block
        const int b0 = kb0 >> 3;              // first of 16 in-blocks
#pragma unroll
        for (int i = 0; i < 4; i++) {
            int idx = tid + i * 256;          // 1024 assignment entries
            int bl = idx >> 6, nl = idx & 63;
            s_cid[bl * 64 + nl] = assign[(size_t)(b0 + bl) * N_DIM + n0 + nl];
        }
        __syncthreads();

        // 1024 output chunks: 64 n-rows x 16 chunks (16B each).
        // Chunk c (0..15): 16-k block t16=c>>1, half=c&1.
        //   half 0 holds ks {0,1,8,9,2,3,10,11}   of the 16-k block
        //   half 1 holds ks {4,5,12,13,6,7,14,15}
        // -> interleave float4 halves of the two in-block centroid rows.
#pragma unroll
        for (int i = 0; i < 4; i++) {
            int l = tid + i * 256;
            int nl = l >> 4;
            int c = l & 15;
            int t16 = c >> 1;
            int half = c & 1;
            int cid0 = s_cid[(2 * t16) * 64 + nl];
            int cid1 = s_cid[(2 * t16 + 1) * 64 + nl];
            float4 v0 = __ldg(reinterpret_cast<const float4*>(
                cent + (size_t)cid0 * 8 + half * 4));
            float4 v1 = __ldg(reinterpret_cast<const float4*>(
                cent + (size_t)cid1 * 8 + half * 4));
            __half2 o[4];
            o[0] = __floats2half2_rn(v0.x, v0.y);
            o[1] = __floats2half2_rn(v1.x, v1.y);
            o[2] = __floats2half2_rn(v0.z, v0.w);
            o[3] = __floats2half2_rn(v1.z, v1.w);
            *reinterpret_cast<uint4*>(
                g_Bp + (size_t)(n0 + nl) * K_DIM + kb0 + c * 8) =
                *reinterpret_cast<uint4*>(o);
        }
    }
}

// ---------------------------------------------------------------------------
// GEMM: grid (N/BN=16, M/BM=8), 512 threads, warp grid 4(m) x 4(n),
// warp tile 32x64, mma.m16n8k16 f16/f32, 4-stage cp.async pipeline.
// Smem rows are 128B (64 fp16); 16B-chunk swizzle: c ^= (row&3)*2.
// ---------------------------------------------------------------------------
__device__ __forceinline__ void load_tile(uint32_t smem_base, int stage,
                                          const __half* __restrict__ Ab,
                                          const __half* __restrict__ Bb,
                                          int kt, int tid) {
    uint32_t sA = smem_base + stage * STAGE_BYTES;
    uint32_t sB = sA + A_BYTES;
    const __half* Ag = Ab + kt * BK;
    const __half* Bg = Bb + kt * BK;
#pragma unroll
    for (int i = 0; i < 2; i++) {            // A: 1024 16B chunks
        int c = tid + i * THREADS;
        int row = c >> 3, ck = c & 7;
        uint32_t dst = sA + row * 128 + (uint32_t)((ck ^ ((row & 3) * 2)) << 4);
        cp_async16(dst, Ag + (size_t)row * K_DIM + ck * 8);
    }
#pragma unroll
    for (int i = 0; i < 4; i++) {            // B: 2048 16B chunks
        int c = tid + i * THREADS;
        int row = c >> 3, ck = c & 7;
        uint32_t dst = sB + row * 128 + (uint32_t)((ck ^ ((row & 3) * 2)) << 4);
        cp_async16(dst, Bg + (size_t)row * K_DIM + ck * 8);
    }
}

__global__ void __launch_bounds__(THREADS, 1)
gemm_kernel(const float* __restrict__ bias, float* __restrict__ out) {
    extern __shared__ char dsm[];
    const uint32_t smem_base = smem_u32(dsm);
    const int tid = threadIdx.x;
    const int lane = tid & 31;
    const int wid = tid >> 5;                // 0..15
    const int gid = lane >> 2;               // 0..7
    const int tig = lane & 3;                // 0..3
    const int wm0 = (wid >> 2) * 32;         // 4 m-slots of 32
    const int wn0 = (wid & 3) * 64;          // 4 n-slots of 64
    const int m0 = blockIdx.y * BM;
    const int n0 = blockIdx.x * BN;

    const __half* Ab = g_Ap + (size_t)m0 * K_DIM;
    const __half* Bb = g_Bp + (size_t)n0 * K_DIM;

    float acc[2][8][4];
#pragma unroll
    for (int mt = 0; mt < 2; mt++)
#pragma unroll
        for (int nt = 0; nt < 8; nt++)
#pragma unroll
            for (int r = 0; r < 4; r++) acc[mt][nt][r] = 0.0f;

    // Prologue: stages 0..2
#pragma unroll
    for (int t = 0; t < STAGES - 1; t++) {
        load_tile(smem_base, t, Ab, Bb, t, tid);
        CP_COMMIT();
    }

    const uint32_t swz_x = (uint32_t)((gid & 3) * 2);
    const uint32_t sub8 = (uint32_t)((tig & 1) << 3);

    for (int kt = 0; kt < NT; kt++) {
        CP_WAIT2();                          // tile kt resident
        __syncthreads();                     // stage kt-1 free everywhere

        int ld = kt + STAGES - 1;
        if (ld < NT) load_tile(smem_base, ld & (STAGES - 1), Ab, Bb, ld, tid);
        CP_COMMIT();

        const char* sa = dsm + (kt & (STAGES - 1)) * STAGE_BYTES;
        const char* sb = sa + A_BYTES;

#pragma unroll
        for (int kb = 0; kb < 4; kb++) {     // four 16-k blocks
            const uint32_t coff =
                (uint32_t)((((kb * 2 + (tig >> 1)) ^ swz_x) << 4) | sub8);
            uint32_t a[2][4];
#pragma unroll
            for (int mt = 0; mt < 2; mt++) {
                int rlo = wm0 + mt * 16 + gid;
                uint2 lo = *reinterpret_cast<const uint2*>(sa + rlo * 128 + coff);
                uint2 hi = *reinterpret_cast<const uint2*>(sa + (rlo + 8) * 128 + coff);
                a[mt][0] = lo.x; a[mt][2] = lo.y;   // row gid
                a[mt][1] = hi.x; a[mt][3] = hi.y;   // row gid+8
            }
            uint32_t bb[8][2];
#pragma unroll
            for (int nt = 0; nt < 8; nt++) {
                int r = wn0 + nt * 8 + gid;
                uint2 v = *reinterpret_cast<const uint2*>(sb + r * 128 + coff);
                bb[nt][0] = v.x; bb[nt][1] = v.y;
            }
#pragma unroll
            for (int mt = 0; mt < 2; mt++)
#pragma unroll
                for (int nt = 0; nt < 8; nt++)
                    mma_f16(acc[mt][nt], a[mt], bb[nt]);
        }
    }

    // Epilogue: c0,c1 -> (row gid, cols tig*2,+1); c2,c3 -> row gid+8.
#pragma unroll
    for (int mt = 0; mt < 2; mt++) {
        int mlo = m0 + wm0 + mt * 16 + gid;
#pragma unroll
        for (int nt = 0; nt < 8; nt++) {
            int n = n0 + wn0 + nt * 8 + tig * 2;
            float bx = __ldg(bias + n);
            float by = __ldg(bias + n + 1);
            float2 v0 = {acc[mt][nt][0] + bx, acc[mt][nt][1] + by};
            float2 v1 = {acc[mt][nt][2] + bx, acc[mt][nt][3] + by};
            *reinterpret_cast<float2*>(out + (size_t)mlo * N_DIM + n) = v0;
            *reinterpret_cast<float2*>(out + (size_t)(mlo + 8) * N_DIM + n) = v1;
        }
    }
}

// ---------------------------------------------------------------------------
extern "C" void kernel_launch(void* const* d_in, const int* in_sizes, int n_in,
                              void* d_out, int out_size) {
    const float* x = nullptr;
    const float* cent = nullptr;
    const float* bias = nullptr;
    const int* assign = nullptr;
    // Inputs by element count: x=4194304, centroids=16384, bias=4096,
    // assignments=2097152, counts=2048 (unused).
    for (int i = 0; i < n_in; i++) {
        switch (in_sizes[i]) {
            case M_DIM * K_DIM:        x = (const float*)d_in[i]; break;
            case 2048 * 8:             cent = (const float*)d_in[i]; break;
            case N_DIM:                bias = (const float*)d_in[i]; break;
            case (K_DIM / 8) * N_DIM:  assign = (const int*)d_in[i]; break;
            default: break;
        }
    }

    static bool attr_done = false;
    if (!attr_done) {
        cudaFuncSetAttribute(gemm_kernel,
                             cudaFuncAttributeMaxDynamicSharedMemorySize, SMEM_TOTAL);
        attr_done = true;
    }

    prep_kernel<<<4096, 256>>>(x, assign, cent);
    gemm_kernel<<<dim3(N_DIM / BN, M_DIM / BM), THREADS, SMEM_TOTAL>>>(
        bias, (float*)d_out);
}

// round 5
// speedup vs baseline: 2.0230x; 1.0313x over previous
#include <cuda_runtime.h>
#include <cuda_fp16.h>
#include <cstdint>

// ============================================================================
// QuantizedLinear: out[1024,4096] = x @ W^T + bias
//   W[o, b*8+j] = centroids[assignments[b*4096 + o], j]
//
// fp16 mma.sync.m16n8k16 (f32 accum). R5: back to 8 warps / 64x64 warp tiles
// (best fragment economy), epoch = 2 ktiles per barrier (32 syncs total),
// register double-buffered fragments to hide LDS latency.
// ============================================================================

#define M_DIM 1024
#define N_DIM 4096
#define K_DIM 4096
#define BM 128
#define BN 256
#define BK 64                            // 64 k per sub-tile -> 128B fp16 rows
#define STAGES 4
#define NT (K_DIM / BK)                  // 64 sub-tiles
#define NEPOCH (NT / 2)                  // 32 epochs (2 sub-tiles each)
#define A_BYTES (BM * 128)               // 16384
#define B_BYTES (BN * 128)               // 32768
#define STAGE_BYTES (A_BYTES + B_BYTES)  // 49152
#define SMEM_TOTAL (STAGES * STAGE_BYTES) // 196608
#define THREADS 256

// fp16 operands, fragment-friendly permuted layout: row-major [row][K]; each
// 16-k block stored in order {0,1,8,9,2,3,10,11, 4,5,12,13,6,7,14,15}.
__device__ __align__(16) __half g_Ap[(size_t)M_DIM * K_DIM];
__device__ __align__(16) __half g_Bp[(size_t)N_DIM * K_DIM];

// ---------------------------------------------------------------------------
__device__ __forceinline__ uint32_t smem_u32(const void* p) {
    uint32_t a;
    asm("{ .reg .u64 t; cvta.to.shared.u64 t, %1; cvt.u32.u64 %0, t; }"
        : "=r"(a) : "l"(p));
    return a;
}

__device__ __forceinline__ void cp_async16(uint32_t s, const void* g) {
    asm volatile("cp.async.cg.shared.global [%0], [%1], 16;" :: "r"(s), "l"(g));
}
#define CP_COMMIT() asm volatile("cp.async.commit_group;" ::: "memory")
#define CP_WAIT0()  asm volatile("cp.async.wait_group 0;" ::: "memory")

__device__ __forceinline__ void mma_f16(float* c, const uint32_t* a, const uint32_t* b) {
    asm volatile(
        "mma.sync.aligned.m16n8k16.row.col.f32.f16.f16.f32 "
        "{%0,%1,%2,%3}, {%4,%5,%6,%7}, {%8,%9}, {%0,%1,%2,%3};"
        : "+f"(c[0]), "+f"(c[1]), "+f"(c[2]), "+f"(c[3])
        : "r"(a[0]), "r"(a[1]), "r"(a[2]), "r"(a[3]), "r"(b[0]), "r"(b[1]));
}

// ---------------------------------------------------------------------------
// Prep (4096 blocks of 256):
//   blocks [0,2048):   x -> g_Ap  (fp16 rn, permuted 16-k blocks)
//   blocks [2048,4096): dequant W -> g_Bp via vectorized centroid LDG.128.
// ---------------------------------------------------------------------------
__global__ void __launch_bounds__(256) prep_kernel(const float* __restrict__ x,
                                                   const int* __restrict__ assign,
                                                   const float* __restrict__ cent) {
    __shared__ int s_cid[16 * 64];
    const int b = blockIdx.x;
    const int tid = threadIdx.x;

    if (b < 2048) {
        int c8 = b * 256 + tid;           // 16B chunk index (8 fp16)
        int m = c8 >> 9;                  // 512 chunks per row
        int ck = c8 & 511;
        int kb = ck >> 1;                 // 16-k block
        int half = ck & 1;
        const float* src = x + (size_t)m * K_DIM + kb * 16 + half * 4;
        __half2 o[4];
        o[0] = __floats2half2_rn(__ldg(src + 0), __ldg(src + 1));
        o[1] = __floats2half2_rn(__ldg(src + 8), __ldg(src + 9));
        o[2] = __floats2half2_rn(__ldg(src + 2), __ldg(src + 3));
        o[3] = __floats2half2_rn(__ldg(src + 10), __ldg(src + 11));
        *reinterpret_cast<uint4*>(g_Ap + (size_t)c8 * 8) =
            *reinterpret_cast<uint4*>(o);
    } else {
        const int wb = b - 2048;
        const int n0 = (wb & 63) * 64;        // 64 out-features per block
        const int kb0 = (wb >> 6) * 128;      // 128 K per block
        const int b0 = kb0 >> 3;              // first of 16 in-blocks
#pragma unroll
        for (int i = 0; i < 4; i++) {
            int idx = tid + i * 256;
            int bl = idx >> 6, nl = idx & 63;
            s_cid[bl * 64 + nl] = assign[(size_t)(b0 + bl) * N_DIM + n0 + nl];
        }
        __syncthreads();

        // Chunk c (0..15): t16=c>>1, half=c&1.
        //   half 0 holds ks {0,1,8,9,2,3,10,11}; half 1 ks {4,5,12,13,6,7,14,15}
#pragma unroll
        for (int i = 0; i < 4; i++) {
            int l = tid + i * 256;
            int nl = l >> 4;
            int c = l & 15;
            int t16 = c >> 1;
            int half = c & 1;
            int cid0 = s_cid[(2 * t16) * 64 + nl];
            int cid1 = s_cid[(2 * t16 + 1) * 64 + nl];
            float4 v0 = __ldg(reinterpret_cast<const float4*>(
                cent + (size_t)cid0 * 8 + half * 4));
            float4 v1 = __ldg(reinterpret_cast<const float4*>(
                cent + (size_t)cid1 * 8 + half * 4));
            __half2 o[4];
            o[0] = __floats2half2_rn(v0.x, v0.y);
            o[1] = __floats2half2_rn(v1.x, v1.y);
            o[2] = __floats2half2_rn(v0.z, v0.w);
            o[3] = __floats2half2_rn(v1.z, v1.w);
            *reinterpret_cast<uint4*>(
                g_Bp + (size_t)(n0 + nl) * K_DIM + kb0 + c * 8) =
                *reinterpret_cast<uint4*>(o);
        }
    }
}

// ---------------------------------------------------------------------------
// GEMM: grid (16,8), 256 threads, warp grid 2(m) x 4(n), warp tile 64x64.
// Smem sub-tile rows 128B; 16B-chunk swizzle: c ^= (row&3)*2.
// ---------------------------------------------------------------------------
__device__ __forceinline__ void load_tile(uint32_t smem_base, int stage,
                                          const __half* __restrict__ Ab,
                                          const __half* __restrict__ Bb,
                                          int kt, int tid) {
    uint32_t sA = smem_base + stage * STAGE_BYTES;
    uint32_t sB = sA + A_BYTES;
    const __half* Ag = Ab + kt * BK;
    const __half* Bg = Bb + kt * BK;
#pragma unroll
    for (int i = 0; i < 4; i++) {            // A: 1024 16B chunks
        int c = tid + i * THREADS;
        int row = c >> 3, ck = c & 7;
        uint32_t dst = sA + row * 128 + (uint32_t)((ck ^ ((row & 3) * 2)) << 4);
        cp_async16(dst, Ag + (size_t)row * K_DIM + ck * 8);
    }
#pragma unroll
    for (int i = 0; i < 8; i++) {            // B: 2048 16B chunks
        int c = tid + i * THREADS;
        int row = c >> 3, ck = c & 7;
        uint32_t dst = sB + row * 128 + (uint32_t)((ck ^ ((row & 3) * 2)) << 4);
        cp_async16(dst, Bg + (size_t)row * K_DIM + ck * 8);
    }
}

__global__ void __launch_bounds__(THREADS, 1)
gemm_kernel(const float* __restrict__ bias, float* __restrict__ out) {
    extern __shared__ char dsm[];
    const uint32_t smem_base = smem_u32(dsm);
    const int tid = threadIdx.x;
    const int lane = tid & 31;
    const int wid = tid >> 5;                // 0..7
    const int gid = lane >> 2;               // 0..7
    const int tig = lane & 3;                // 0..3
    const int wm0 = (wid >> 2) * 64;         // 2 m-slots of 64
    const int wn0 = (wid & 3) * 64;          // 4 n-slots of 64
    const int m0 = blockIdx.y * BM;
    const int n0 = blockIdx.x * BN;

    const __half* Ab = g_Ap + (size_t)m0 * K_DIM;
    const __half* Bb = g_Bp + (size_t)n0 * K_DIM;

    float acc[4][8][4];
#pragma unroll
    for (int mt = 0; mt < 4; mt++)
#pragma unroll
        for (int nt = 0; nt < 8; nt++)
#pragma unroll
            for (int r = 0; r < 4; r++) acc[mt][nt][r] = 0.0f;

    const uint32_t swz_x = (uint32_t)((gid & 3) * 2);
    const uint32_t sub8 = (uint32_t)((tig & 1) << 3);

    // Fragment double buffers
    uint32_t af[2][4][4];
    uint32_t bf[2][8][2];

    // Load fragments for 16-k block kbl (0..3) of the sub-tile at (sa,sb).
    #define FRAG_LOAD(B, sa, sb, kbl)                                          \
    do {                                                                       \
        const uint32_t coff =                                                  \
            (uint32_t)(((((kbl) * 2 + (tig >> 1)) ^ swz_x) << 4) | sub8);      \
        _Pragma("unroll")                                                      \
        for (int mt = 0; mt < 4; mt++) {                                       \
            int rlo = wm0 + mt * 16 + gid;                                     \
            uint2 lo = *reinterpret_cast<const uint2*>((sa) + rlo * 128 + coff); \
            uint2 hi = *reinterpret_cast<const uint2*>((sa) + (rlo + 8) * 128 + coff); \
            af[B][mt][0] = lo.x; af[B][mt][2] = lo.y;                          \
            af[B][mt][1] = hi.x; af[B][mt][3] = hi.y;                          \
        }                                                                      \
        _Pragma("unroll")                                                      \
        for (int nt = 0; nt < 8; nt++) {                                       \
            int r = wn0 + nt * 8 + gid;                                        \
            uint2 v = *reinterpret_cast<const uint2*>((sb) + r * 128 + coff);  \
            bf[B][nt][0] = v.x; bf[B][nt][1] = v.y;                            \
        }                                                                      \
    } while (0)

    // Prologue: load sub-tiles 0,1 (epoch 0) as one group.
    load_tile(smem_base, 0, Ab, Bb, 0, tid);
    load_tile(smem_base, 1, Ab, Bb, 1, tid);
    CP_COMMIT();

    for (int p = 0; p < NEPOCH; p++) {
        CP_WAIT0();                          // epoch p's pair resident
        __syncthreads();                     // prev epoch's stages free

        const char* saA[2] = {dsm + ((2 * p) & 3) * STAGE_BYTES,
                              dsm + ((2 * p + 1) & 3) * STAGE_BYTES};

        // Warm fragment pipeline with kb=0, then issue next pair's cp.async
        // (overlaps with this epoch's MMAs).
        FRAG_LOAD(0, saA[0], saA[0] + A_BYTES, 0);
        if (p + 1 < NEPOCH) {
            load_tile(smem_base, (2 * p + 2) & 3, Ab, Bb, 2 * p + 2, tid);
            load_tile(smem_base, (2 * p + 3) & 3, Ab, Bb, 2 * p + 3, tid);
            CP_COMMIT();
        }

#pragma unroll
        for (int kb = 0; kb < 8; kb++) {     // 8 x 16-k blocks per epoch
            if (kb < 7) {
                const char* nsa = saA[(kb + 1) >> 2];
                FRAG_LOAD((kb + 1) & 1, nsa, nsa + A_BYTES, (kb + 1) & 3);
            }
            const int B = kb & 1;
#pragma unroll
            for (int mt = 0; mt < 4; mt++)
#pragma unroll
                for (int nt = 0; nt < 8; nt++)
                    mma_f16(acc[mt][nt], af[B][mt], bf[B][nt]);
        }
    }

    // Epilogue: c0,c1 -> (row gid, cols tig*2,+1); c2,c3 -> row gid+8.
#pragma unroll
    for (int mt = 0; mt < 4; mt++) {
        int mlo = m0 + wm0 + mt * 16 + gid;
#pragma unroll
        for (int nt = 0; nt < 8; nt++) {
            int n = n0 + wn0 + nt * 8 + tig * 2;
            float bx = __ldg(bias + n);
            float by = __ldg(bias + n + 1);
            float2 v0 = {acc[mt][nt][0] + bx, acc[mt][nt][1] + by};
            float2 v1 = {acc[mt][nt][2] + bx, acc[mt][nt][3] + by};
            *reinterpret_cast<float2*>(out + (size_t)mlo * N_DIM + n) = v0;
            *reinterpret_cast<float2*>(out + (size_t)(mlo + 8) * N_DIM + n) = v1;
        }
    }
}

// ---------------------------------------------------------------------------
extern "C" void kernel_launch(void* const* d_in, const int* in_sizes, int n_in,
                              void* d_out, int out_size) {
    const float* x = nullptr;
    const float* cent = nullptr;
    const float* bias = nullptr;
    const int* assign = nullptr;
    // Inputs by element count: x=4194304, centroids=16384, bias=4096,
    // assignments=2097152, counts=2048 (unused).
    for (int i = 0; i < n_in; i++) {
        switch (in_sizes[i]) {
            case M_DIM * K_DIM:        x = (const float*)d_in[i]; break;
            case 2048 * 8:             cent = (const float*)d_in[i]; break;
            case N_DIM:                bias = (const float*)d_in[i]; break;
            case (K_DIM / 8) * N_DIM:  assign = (const int*)d_in[i]; break;
            default: break;
        }
    }

    static bool attr_done = false;
    if (!attr_done) {
        cudaFuncSetAttribute(gemm_kernel,
                             cudaFuncAttributeMaxDynamicSharedMemorySize, SMEM_TOTAL);
        attr_done = true;
    }

    prep_kernel<<<4096, 256>>>(x, assign, cent);
    gemm_kernel<<<dim3(N_DIM / BN, M_DIM / BM), THREADS, SMEM_TOTAL>>>(
        bias, (float*)d_out);
}

// round 6
// speedup vs baseline: 2.0995x; 1.0378x over previous
#include <cuda_runtime.h>
#include <cuda_fp16.h>
#include <cstdint>

// ============================================================================
// QuantizedLinear: out[1024,4096] = x @ W^T + bias
//   W[o, b*8+j] = centroids[assignments[b*4096 + o], j]
//
// fp16 mma.sync.m16n8k16 (f32 accum). R6: 2 independent CTAs per SM
// (BM=BN=128, 128 threads, 4 warps, 64x64 warp tiles, 2-stage 64KB smem)
// so barrier/wait stalls of one CTA are covered by the other CTA's warps.
// ============================================================================

#define M_DIM 1024
#define N_DIM 4096
#define K_DIM 4096
#define BM 128
#define BN 128
#define BK 64                            // 64 k per tile -> 128B fp16 rows
#define STAGES 2
#define NT (K_DIM / BK)                  // 64 k-tiles
#define A_BYTES (BM * 128)               // 16384
#define B_BYTES (BN * 128)               // 16384
#define STAGE_BYTES (A_BYTES + B_BYTES)  // 32768
#define SMEM_TOTAL (STAGES * STAGE_BYTES) // 65536
#define THREADS 128

// fp16 operands, fragment-friendly permuted layout: row-major [row][K]; each
// 16-k block stored in order {0,1,8,9,2,3,10,11, 4,5,12,13,6,7,14,15}.
__device__ __align__(16) __half g_Ap[(size_t)M_DIM * K_DIM];
__device__ __align__(16) __half g_Bp[(size_t)N_DIM * K_DIM];

// ---------------------------------------------------------------------------
__device__ __forceinline__ uint32_t smem_u32(const void* p) {
    uint32_t a;
    asm("{ .reg .u64 t; cvta.to.shared.u64 t, %1; cvt.u32.u64 %0, t; }"
        : "=r"(a) : "l"(p));
    return a;
}

__device__ __forceinline__ void cp_async16(uint32_t s, const void* g) {
    asm volatile("cp.async.cg.shared.global [%0], [%1], 16;" :: "r"(s), "l"(g));
}
#define CP_COMMIT() asm volatile("cp.async.commit_group;" ::: "memory")
#define CP_WAIT0()  asm volatile("cp.async.wait_group 0;" ::: "memory")

__device__ __forceinline__ void mma_f16(float* c, const uint32_t* a, const uint32_t* b) {
    asm volatile(
        "mma.sync.aligned.m16n8k16.row.col.f32.f16.f16.f32 "
        "{%0,%1,%2,%3}, {%4,%5,%6,%7}, {%8,%9}, {%0,%1,%2,%3};"
        : "+f"(c[0]), "+f"(c[1]), "+f"(c[2]), "+f"(c[3])
        : "r"(a[0]), "r"(a[1]), "r"(a[2]), "r"(a[3]), "r"(b[0]), "r"(b[1]));
}

// ---------------------------------------------------------------------------
// Prep (4096 blocks of 256):
//   blocks [0,2048):   x -> g_Ap  (fp16 rn, permuted 16-k blocks)
//   blocks [2048,4096): dequant W -> g_Bp via vectorized centroid LDG.128.
// ---------------------------------------------------------------------------
__global__ void __launch_bounds__(256) prep_kernel(const float* __restrict__ x,
                                                   const int* __restrict__ assign,
                                                   const float* __restrict__ cent) {
    __shared__ int s_cid[16 * 64];
    const int b = blockIdx.x;
    const int tid = threadIdx.x;

    if (b < 2048) {
        int c8 = b * 256 + tid;           // 16B chunk index (8 fp16)
        int m = c8 >> 9;                  // 512 chunks per row
        int ck = c8 & 511;
        int kb = ck >> 1;                 // 16-k block
        int half = ck & 1;
        const float* src = x + (size_t)m * K_DIM + kb * 16 + half * 4;
        __half2 o[4];
        o[0] = __floats2half2_rn(__ldg(src + 0), __ldg(src + 1));
        o[1] = __floats2half2_rn(__ldg(src + 8), __ldg(src + 9));
        o[2] = __floats2half2_rn(__ldg(src + 2), __ldg(src + 3));
        o[3] = __floats2half2_rn(__ldg(src + 10), __ldg(src + 11));
        *reinterpret_cast<uint4*>(g_Ap + (size_t)c8 * 8) =
            *reinterpret_cast<uint4*>(o);
    } else {
        const int wb = b - 2048;
        const int n0 = (wb & 63) * 64;        // 64 out-features per block
        const int kb0 = (wb >> 6) * 128;      // 128 K per block
        const int b0 = kb0 >> 3;              // first of 16 in-blocks
#pragma unroll
        for (int i = 0; i < 4; i++) {
            int idx = tid + i * 256;
            int bl = idx >> 6, nl = idx & 63;
            s_cid[bl * 64 + nl] = assign[(size_t)(b0 + bl) * N_DIM + n0 + nl];
        }
        __syncthreads();

        // Chunk c (0..15): t16=c>>1, half=c&1.
        //   half 0 holds ks {0,1,8,9,2,3,10,11}; half 1 ks {4,5,12,13,6,7,14,15}
#pragma unroll
        for (int i = 0; i < 4; i++) {
            int l = tid + i * 256;
            int nl = l >> 4;
            int c = l & 15;
            int t16 = c >> 1;
            int half = c & 1;
            int cid0 = s_cid[(2 * t16) * 64 + nl];
            int cid1 = s_cid[(2 * t16 + 1) * 64 + nl];
            float4 v0 = __ldg(reinterpret_cast<const float4*>(
                cent + (size_t)cid0 * 8 + half * 4));
            float4 v1 = __ldg(reinterpret_cast<const float4*>(
                cent + (size_t)cid1 * 8 + half * 4));
            __half2 o[4];
            o[0] = __floats2half2_rn(v0.x, v0.y);
            o[1] = __floats2half2_rn(v1.x, v1.y);
            o[2] = __floats2half2_rn(v0.z, v0.w);
            o[3] = __floats2half2_rn(v1.z, v1.w);
            *reinterpret_cast<uint4*>(
                g_Bp + (size_t)(n0 + nl) * K_DIM + kb0 + c * 8) =
                *reinterpret_cast<uint4*>(o);
        }
    }
}

// ---------------------------------------------------------------------------
// GEMM: grid (32, 8), 128 threads, warp grid 2(m) x 2(n), warp tile 64x64.
// Smem tile rows 128B; 16B-chunk swizzle: c ^= (row&3)*2. 2-stage pipeline.
// ---------------------------------------------------------------------------
__device__ __forceinline__ void load_tile(uint32_t smem_base, int stage,
                                          const __half* __restrict__ Ab,
                                          const __half* __restrict__ Bb,
                                          int kt, int tid) {
    uint32_t sA = smem_base + stage * STAGE_BYTES;
    uint32_t sB = sA + A_BYTES;
    const __half* Ag = Ab + kt * BK;
    const __half* Bg = Bb + kt * BK;
#pragma unroll
    for (int i = 0; i < 8; i++) {            // A: 1024 16B chunks
        int c = tid + i * THREADS;
        int row = c >> 3, ck = c & 7;
        uint32_t dst = sA + row * 128 + (uint32_t)((ck ^ ((row & 3) * 2)) << 4);
        cp_async16(dst, Ag + (size_t)row * K_DIM + ck * 8);
    }
#pragma unroll
    for (int i = 0; i < 8; i++) {            // B: 1024 16B chunks
        int c = tid + i * THREADS;
        int row = c >> 3, ck = c & 7;
        uint32_t dst = sB + row * 128 + (uint32_t)((ck ^ ((row & 3) * 2)) << 4);
        cp_async16(dst, Bg + (size_t)row * K_DIM + ck * 8);
    }
}

__global__ void __launch_bounds__(THREADS, 2)
gemm_kernel(const float* __restrict__ bias, float* __restrict__ out) {
    extern __shared__ char dsm[];
    const uint32_t smem_base = smem_u32(dsm);
    const int tid = threadIdx.x;
    const int lane = tid & 31;
    const int wid = tid >> 5;                // 0..3
    const int gid = lane >> 2;               // 0..7
    const int tig = lane & 3;                // 0..3
    const int wm0 = (wid >> 1) * 64;         // 2 m-slots of 64
    const int wn0 = (wid & 1) * 64;          // 2 n-slots of 64
    const int m0 = blockIdx.y * BM;
    const int n0 = blockIdx.x * BN;

    const __half* Ab = g_Ap + (size_t)m0 * K_DIM;
    const __half* Bb = g_Bp + (size_t)n0 * K_DIM;

    float acc[4][8][4];
#pragma unroll
    for (int mt = 0; mt < 4; mt++)
#pragma unroll
        for (int nt = 0; nt < 8; nt++)
#pragma unroll
            for (int r = 0; r < 4; r++) acc[mt][nt][r] = 0.0f;

    const uint32_t swz_x = (uint32_t)((gid & 3) * 2);
    const uint32_t sub8 = (uint32_t)((tig & 1) << 3);

    // Fragment double buffers (per 16-k block)
    uint32_t af[2][4][4];
    uint32_t bf[2][8][2];

    #define FRAG_LOAD(B, sa, sb, kbl)                                          \
    do {                                                                       \
        const uint32_t coff =                                                  \
            (uint32_t)(((((kbl) * 2 + (tig >> 1)) ^ swz_x) << 4) | sub8);      \
        _Pragma("unroll")                                                      \
        for (int mt = 0; mt < 4; mt++) {                                       \
            int rlo = wm0 + mt * 16 + gid;                                     \
            uint2 lo = *reinterpret_cast<const uint2*>((sa) + rlo * 128 + coff); \
            uint2 hi = *reinterpret_cast<const uint2*>((sa) + (rlo + 8) * 128 + coff); \
            af[B][mt][0] = lo.x; af[B][mt][2] = lo.y;                          \
            af[B][mt][1] = hi.x; af[B][mt][3] = hi.y;                          \
        }                                                                      \
        _Pragma("unroll")                                                      \
        for (int nt = 0; nt < 8; nt++) {                                       \
            int r = wn0 + nt * 8 + gid;                                        \
            uint2 v = *reinterpret_cast<const uint2*>((sb) + r * 128 + coff);  \
            bf[B][nt][0] = v.x; bf[B][nt][1] = v.y;                            \
        }                                                                      \
    } while (0)

    // Prologue: stage 0 <- tile 0
    load_tile(smem_base, 0, Ab, Bb, 0, tid);
    CP_COMMIT();

    for (int kt = 0; kt < NT; kt++) {
        CP_WAIT0();                          // tile kt resident
        __syncthreads();                     // all warps done with other stage

        if (kt + 1 < NT) {                   // load next tile into freed stage
            load_tile(smem_base, (kt + 1) & 1, Ab, Bb, kt + 1, tid);
            CP_COMMIT();
        }

        const char* sa = dsm + (kt & 1) * STAGE_BYTES;
        const char* sb = sa + A_BYTES;

        FRAG_LOAD(0, sa, sb, 0);             // warm kb0
#pragma unroll
        for (int kb = 0; kb < 4; kb++) {     // four 16-k blocks
            if (kb < 3) FRAG_LOAD((kb + 1) & 1, sa, sb, kb + 1);
            const int B = kb & 1;
#pragma unroll
            for (int mt = 0; mt < 4; mt++)
#pragma unroll
                for (int nt = 0; nt < 8; nt++)
                    mma_f16(acc[mt][nt], af[B][mt], bf[B][nt]);
        }
    }

    // Epilogue: c0,c1 -> (row gid, cols tig*2,+1); c2,c3 -> row gid+8.
#pragma unroll
    for (int mt = 0; mt < 4; mt++) {
        int mlo = m0 + wm0 + mt * 16 + gid;
#pragma unroll
        for (int nt = 0; nt < 8; nt++) {
            int n = n0 + wn0 + nt * 8 + tig * 2;
            float bx = __ldg(bias + n);
            float by = __ldg(bias + n + 1);
            float2 v0 = {acc[mt][nt][0] + bx, acc[mt][nt][1] + by};
            float2 v1 = {acc[mt][nt][2] + bx, acc[mt][nt][3] + by};
            *reinterpret_cast<float2*>(out + (size_t)mlo * N_DIM + n) = v0;
            *reinterpret_cast<float2*>(out + (size_t)(mlo + 8) * N_DIM + n) = v1;
        }
    }
}

// ---------------------------------------------------------------------------
extern "C" void kernel_launch(void* const* d_in, const int* in_sizes, int n_in,
                              void* d_out, int out_size) {
    const float* x = nullptr;
    const float* cent = nullptr;
    const float* bias = nullptr;
    const int* assign = nullptr;
    // Inputs by element count: x=4194304, centroids=16384, bias=4096,
    // assignments=2097152, counts=2048 (unused).
    for (int i = 0; i < n_in; i++) {
        switch (in_sizes[i]) {
            case M_DIM * K_DIM:        x = (const float*)d_in[i]; break;
            case 2048 * 8:             cent = (const float*)d_in[i]; break;
            case N_DIM:                bias = (const float*)d_in[i]; break;
            case (K_DIM / 8) * N_DIM:  assign = (const int*)d_in[i]; break;
            default: break;
        }
    }

    static bool attr_done = false;
    if (!attr_done) {
        cudaFuncSetAttribute(gemm_kernel,
                             cudaFuncAttributeMaxDynamicSharedMemorySize, SMEM_TOTAL);
        attr_done = true;
    }

    prep_kernel<<<4096, 256>>>(x, assign, cent);
    gemm_kernel<<<dim3(N_DIM / BN, M_DIM / BM), THREADS, SMEM_TOTAL>>>(
        bias, (float*)d_out);
}